// round 12
// baseline (speedup 1.0000x reference)
#include <cuda_runtime.h>
#include <cuda_fp16.h>
#include <mma.h>
#include <math.h>

using namespace nvcuda;

#define N_NODES 100000
#define N_PAD   100096
#define N_EDGES 1600000
#define CHN 128
#define OUTCH 64
#define SCAN_T 512
#define SCAN_NB ((N_NODES + SCAN_T - 1) / SCAN_T)   // 196

// ---------------- device scratch ------------------------------------------
__device__ int    g_cnt[N_NODES];        // zeroed at end of k_scan3 (self-restoring)
__device__ int    g_row[N_NODES + 1];
__device__ int    g_cur[N_NODES];
__device__ float  g_dis[N_NODES];
__device__ int    g_csr[N_EDGES];
__device__ int    g_bsum[SCAN_NB];
__device__ __half g_hs[N_PAD * CHN];
__device__ __half g_x1[N_PAD * CHN];
__device__ __half g_x2[N_PAD * CHN];

// ---------------- per-block dtype sniff ------------------------------------
// int64 edges with ids < 2^31 have every odd 32-bit word == 0.
__device__ __forceinline__ int sniff_is64(const void* edges) {
    const int* p = (const int*)edges;
    int z = 0;
#pragma unroll
    for (int u = 0; u < 16; u++) z += (p[2 * u + 1] == 0);
    return z > 8;
}

__global__ void k_hist(const void* __restrict__ edges) {
    int is64 = sniff_is64(edges);
    int base = (blockIdx.x * blockDim.x + threadIdx.x) * 8;
#pragma unroll
    for (int u = 0; u < 8; u++) {
        int i = base + u;
        if (i >= N_EDGES) break;
        int d;
        if (is64) d = (int)((const long long*)edges)[N_EDGES + i];
        else      d = ((const int*)edges)[N_EDGES + i];
        atomicAdd(&g_cnt[d], 1);
    }
}

// ---------------- 2-kernel scan --------------------------------------------
__global__ void k_scan1() {
    __shared__ int s[SCAN_T];
    int i = blockIdx.x * SCAN_T + threadIdx.x;
    int v = (i < N_NODES) ? g_cnt[i] : 0;
    s[threadIdx.x] = v;
    __syncthreads();
    for (int off = SCAN_T / 2; off > 0; off >>= 1) {
        if (threadIdx.x < off) s[threadIdx.x] += s[threadIdx.x + off];
        __syncthreads();
    }
    if (threadIdx.x == 0) g_bsum[blockIdx.x] = s[0];
}

// scan3: each block scans the 196 block sums itself (removes k_scan2),
// produces row/cur/dis, and zeroes g_cnt for the next graph replay.
__global__ void k_scan3() {
    __shared__ int s[SCAN_T];
    __shared__ int bs[256];
    int t = threadIdx.x;
    if (t < 256) bs[t] = (t < SCAN_NB) ? g_bsum[t] : 0;
    __syncthreads();
    for (int off = 1; off < 256; off <<= 1) {
        int u = (t >= off && t < 256) ? bs[t - off] : 0;
        __syncthreads();
        if (t < 256) bs[t] += u;
        __syncthreads();
    }
    int boff = (blockIdx.x > 0) ? bs[blockIdx.x - 1] : 0;
    __syncthreads();

    int i = blockIdx.x * SCAN_T + t;
    int c = (i < N_NODES) ? g_cnt[i] : 0;
    s[t] = c;
    __syncthreads();
    for (int off = 1; off < SCAN_T; off <<= 1) {
        int u = (t >= off) ? s[t - off] : 0;
        __syncthreads();
        s[t] += u;
        __syncthreads();
    }
    if (i < N_NODES) {
        int excl = boff + s[t] - c;
        g_row[i] = excl;
        g_cur[i] = excl;
        g_dis[i] = rsqrtf((float)(c + 1));
        g_cnt[i] = 0;                       // restore for next replay
        if (i == N_NODES - 1) g_row[N_NODES] = excl + c;
    }
}

__global__ void k_fill(const void* __restrict__ edges) {
    int is64 = sniff_is64(edges);
    int base = (blockIdx.x * blockDim.x + threadIdx.x) * 8;
#pragma unroll
    for (int u = 0; u < 8; u++) {
        int i = base + u;
        if (i >= N_EDGES) break;
        int sN, dN;
        if (is64) {
            const long long* p = (const long long*)edges;
            sN = (int)p[i]; dN = (int)p[N_EDGES + i];
        } else {
            const int* p = (const int*)edges;
            sN = p[i]; dN = p[N_EDGES + i];
        }
        int idx = atomicAdd(&g_cur[dN], 1);
        g_csr[idx] = sN;
    }
}

// ---------------- tf32 GEMM (R7 structure) --------------------------------
#define AS_FLOATS (192 * 36)
#define BS_FLOATS (32 * 136)

template <typename AT>
__global__ __launch_bounds__(256) void gemm_tf32(
    const AT* __restrict__ A, const float* __restrict__ B,
    __half* __restrict__ out, const float* __restrict__ dis, int M)
{
    __shared__ float pool[AS_FLOATS + BS_FLOATS];   // 45056 B
    float (*As)[36]  = (float(*)[36])pool;
    float (*Bs)[136] = (float(*)[136])(pool + AS_FLOATS);
    float (*stage)[16][20] = (float(*)[16][20])pool;   // aliases As (dead)

    int tid = threadIdx.x;
    int wid = tid >> 5;
    int lane = tid & 31;
    int wm = wid & 3;
    int wn = wid >> 2;
    int bm = blockIdx.x * 192;

    wmma::fragment<wmma::accumulator, 16, 16, 8, float> acc[3][4];
#pragma unroll
    for (int i = 0; i < 3; i++)
#pragma unroll
        for (int j = 0; j < 4; j++) wmma::fill_fragment(acc[i][j], 0.f);

    for (int k0 = 0; k0 < 128; k0 += 32) {
#pragma unroll
        for (int h = 0; h < 6; h++) {
            int i4 = tid + h * 256;
            int r = i4 >> 3, c = (i4 & 7) * 4;
            float4 v = make_float4(0.f, 0.f, 0.f, 0.f);
            if (bm + r < M) {
                if constexpr (sizeof(AT) == 4) {
                    v = *(const float4*)((const float*)A + (long)(bm + r) * 128 + k0 + c);
                } else {
                    uint2 raw = *(const uint2*)((const __half*)A + (long)(bm + r) * 128 + k0 + c);
                    float2 a = __half22float2(*(__half2*)&raw.x);
                    float2 b = __half22float2(*(__half2*)&raw.y);
                    v = make_float4(a.x, a.y, b.x, b.y);
                }
            }
            As[r][c + 0] = wmma::__float_to_tf32(v.x);
            As[r][c + 1] = wmma::__float_to_tf32(v.y);
            As[r][c + 2] = wmma::__float_to_tf32(v.z);
            As[r][c + 3] = wmma::__float_to_tf32(v.w);
        }
#pragma unroll
        for (int h = 0; h < 4; h++) {
            int i4 = tid + h * 256;
            int r = i4 >> 5, c = (i4 & 31) * 4;
            float4 v = *(const float4*)(B + (long)(k0 + r) * 128 + c);
            Bs[r][c + 0] = wmma::__float_to_tf32(v.x);
            Bs[r][c + 1] = wmma::__float_to_tf32(v.y);
            Bs[r][c + 2] = wmma::__float_to_tf32(v.z);
            Bs[r][c + 3] = wmma::__float_to_tf32(v.w);
        }
        __syncthreads();
#pragma unroll
        for (int kk = 0; kk < 4; kk++) {
            wmma::fragment<wmma::matrix_a, 16, 16, 8, wmma::precision::tf32, wmma::row_major> af[3];
            wmma::fragment<wmma::matrix_b, 16, 16, 8, wmma::precision::tf32, wmma::row_major> bf[4];
#pragma unroll
            for (int i = 0; i < 3; i++)
                wmma::load_matrix_sync(af[i], &As[wm * 48 + i * 16][kk * 8], 36);
#pragma unroll
            for (int j = 0; j < 4; j++)
                wmma::load_matrix_sync(bf[j], &Bs[kk * 8][wn * 64 + j * 16], 136);
#pragma unroll
            for (int i = 0; i < 3; i++)
#pragma unroll
                for (int j = 0; j < 4; j++)
                    wmma::mma_sync(acc[i][j], af[i], bf[j], acc[i][j]);
        }
        __syncthreads();
    }
#pragma unroll
    for (int i = 0; i < 3; i++)
#pragma unroll
        for (int j = 0; j < 4; j++) {
            wmma::store_matrix_sync(&stage[wid][0][0], acc[i][j], 20, wmma::mem_row_major);
            __syncwarp();
            int r = bm + wm * 48 + i * 16 + (lane >> 1);
            float dsc = (r < M) ? dis[r] : 0.f;
            const float* srow = &stage[wid][lane >> 1][(lane & 1) * 8];
            __half2 h0 = __float22half2_rn(make_float2(srow[0] * dsc, srow[1] * dsc));
            __half2 h1 = __float22half2_rn(make_float2(srow[2] * dsc, srow[3] * dsc));
            __half2 h2 = __float22half2_rn(make_float2(srow[4] * dsc, srow[5] * dsc));
            __half2 h3 = __float22half2_rn(make_float2(srow[6] * dsc, srow[7] * dsc));
            uint4 pack;
            pack.x = *(unsigned*)&h0;
            pack.y = *(unsigned*)&h1;
            pack.z = *(unsigned*)&h2;
            pack.w = *(unsigned*)&h3;
            *(uint4*)(out + (long)r * 128 + wn * 64 + j * 16 + (lane & 1) * 8) = pack;
            __syncwarp();
        }
}

// ---------------- tf32 output GEMM: (x1+x2)[M,128] @ Wo[128,64] + bo ------
__global__ __launch_bounds__(256) void gemm_out_tf32(
    const __half* __restrict__ A1, const __half* __restrict__ A2,
    const float* __restrict__ B, const float* __restrict__ bias,
    float* __restrict__ out, int M)
{
    __shared__ float As[128][36];
    __shared__ float Bs[32][72];
    __shared__ float Bt[16][72];
    int tid = threadIdx.x;
    int wid = tid >> 5;
    int bm = blockIdx.x * 128;

    for (int i = tid; i < 16 * 64; i += 256) Bt[i >> 6][i & 63] = bias[i & 63];
    __syncthreads();

    wmma::fragment<wmma::accumulator, 16, 16, 8, float> acc[4];
#pragma unroll
    for (int j = 0; j < 4; j++)
        wmma::load_matrix_sync(acc[j], &Bt[0][j * 16], 72, wmma::mem_row_major);

    for (int k0 = 0; k0 < 128; k0 += 32) {
#pragma unroll
        for (int h = 0; h < 4; h++) {
            int i4 = tid + h * 256;
            int r = i4 >> 3, c = (i4 & 7) * 4;
            float4 v = make_float4(0.f, 0.f, 0.f, 0.f);
            if (bm + r < M) {
                uint2 r1 = *(const uint2*)(A1 + (long)(bm + r) * 128 + k0 + c);
                uint2 r2 = *(const uint2*)(A2 + (long)(bm + r) * 128 + k0 + c);
                float2 a1 = __half22float2(*(__half2*)&r1.x);
                float2 b1 = __half22float2(*(__half2*)&r1.y);
                float2 a2 = __half22float2(*(__half2*)&r2.x);
                float2 b2 = __half22float2(*(__half2*)&r2.y);
                v.x = a1.x + a2.x; v.y = a1.y + a2.y;
                v.z = b1.x + b2.x; v.w = b1.y + b2.y;
            }
            As[r][c + 0] = wmma::__float_to_tf32(v.x);
            As[r][c + 1] = wmma::__float_to_tf32(v.y);
            As[r][c + 2] = wmma::__float_to_tf32(v.z);
            As[r][c + 3] = wmma::__float_to_tf32(v.w);
        }
        {
            int r = tid >> 4, c = (tid & 15) * 4;
            float4 v = *(const float4*)(B + (long)(k0 + r) * 64 + c);
            Bs[r][c + 0] = wmma::__float_to_tf32(v.x);
            Bs[r][c + 1] = wmma::__float_to_tf32(v.y);
            Bs[r][c + 2] = wmma::__float_to_tf32(v.z);
            Bs[r][c + 3] = wmma::__float_to_tf32(v.w);
            r = (tid + 256) >> 4; c = ((tid + 256) & 15) * 4;
            v = *(const float4*)(B + (long)(k0 + r) * 64 + c);
            Bs[r][c + 0] = wmma::__float_to_tf32(v.x);
            Bs[r][c + 1] = wmma::__float_to_tf32(v.y);
            Bs[r][c + 2] = wmma::__float_to_tf32(v.z);
            Bs[r][c + 3] = wmma::__float_to_tf32(v.w);
        }
        __syncthreads();
#pragma unroll
        for (int kk = 0; kk < 4; kk++) {
            wmma::fragment<wmma::matrix_a, 16, 16, 8, wmma::precision::tf32, wmma::row_major> af;
            wmma::fragment<wmma::matrix_b, 16, 16, 8, wmma::precision::tf32, wmma::row_major> bf[4];
            wmma::load_matrix_sync(af, &As[wid * 16][kk * 8], 36);
#pragma unroll
            for (int j = 0; j < 4; j++)
                wmma::load_matrix_sync(bf[j], &Bs[kk * 8][j * 16], 72);
#pragma unroll
            for (int j = 0; j < 4; j++)
                wmma::mma_sync(acc[j], af, bf[j], acc[j]);
        }
        __syncthreads();
    }
    int r = bm + wid * 16;
    if (r + 16 <= M) {
#pragma unroll
        for (int j = 0; j < 4; j++)
            wmma::store_matrix_sync(out + (long)r * 64 + j * 16,
                                    acc[j], 64, wmma::mem_row_major);
    }
}

// ---------------- aggregation: warp/node, masked 8-wide batches -----------
__device__ __forceinline__ float4 gather_h(const __half* hs, int s, int lane) {
    uint2 raw = *(const uint2*)(hs + (long)s * 128 + lane * 4);
    float2 a = __half22float2(*(__half2*)&raw.x);
    float2 b = __half22float2(*(__half2*)&raw.y);
    return make_float4(a.x, a.y, b.x, b.y);
}

__global__ __launch_bounds__(256) void aggregate_s(
    const __half* __restrict__ hs, const float* __restrict__ bias,
    __half* __restrict__ xo)
{
    int gw = (blockIdx.x * blockDim.x + threadIdx.x) >> 5;
    int lane = threadIdx.x & 31;
    if (gw >= N_NODES) return;
    int beg = g_row[gw];
    int end = g_row[gw + 1];
    float4 acc = gather_h(hs, gw, lane);   // self term, pre-scaled
    for (int e = beg; e < end; e += 8) {
        int idx[8]; float w[8];
#pragma unroll
        for (int u = 0; u < 8; u++) {
            int ee = e + u;
            bool ok = ee < end;
            idx[u] = ok ? g_csr[ee] : gw;   // masked lanes hit hot self row
            w[u] = ok ? 1.f : 0.f;
        }
        float4 v[8];
#pragma unroll
        for (int u = 0; u < 8; u++) v[u] = gather_h(hs, idx[u], lane);
#pragma unroll
        for (int u = 0; u < 8; u++) {
            acc.x += v[u].x * w[u];
            acc.y += v[u].y * w[u];
            acc.z += v[u].z * w[u];
            acc.w += v[u].w * w[u];
        }
    }
    float dd = g_dis[gw];
    float4 b = *(const float4*)(bias + lane * 4);
    __half2 o0 = __float22half2_rn(make_float2(
        fmaxf(acc.x * dd + b.x, 0.f), fmaxf(acc.y * dd + b.y, 0.f)));
    __half2 o1 = __float22half2_rn(make_float2(
        fmaxf(acc.z * dd + b.z, 0.f), fmaxf(acc.w * dd + b.w, 0.f)));
    uint2 pack;
    pack.x = *(unsigned*)&o0;
    pack.y = *(unsigned*)&o1;
    *(uint2*)(xo + (long)gw * 128 + lane * 4) = pack;
}

// ---------------- launch ---------------------------------------------------
extern "C" void kernel_launch(void* const* d_in, const int* in_sizes, int n_in,
                              void* d_out, int out_size)
{
    const float* x  = (const float*)d_in[0];
    const void*  ei = d_in[1];
    const float* W1 = (const float*)d_in[2];
    const float* b1 = (const float*)d_in[3];
    const float* W2 = (const float*)d_in[4];
    const float* b2 = (const float*)d_in[5];
    const float* Wo = (const float*)d_in[6];
    const float* bo = (const float*)d_in[7];
    float* out = (float*)d_out;

    __half *hs, *x1, *x2;
    float* dis;
    cudaGetSymbolAddress((void**)&hs,  g_hs);
    cudaGetSymbolAddress((void**)&x1,  g_x1);
    cudaGetSymbolAddress((void**)&x2,  g_x2);
    cudaGetSymbolAddress((void**)&dis, g_dis);

    const int M = N_NODES;
    int gB  = (M + 191) / 192;
    int gBo = (M + 127) / 128;
    int gE8 = (N_EDGES + 2047) / 2048;
    int gAg = (M * 32 + 255) / 256;

    k_hist<<<gE8, 256>>>(ei);
    k_scan1<<<SCAN_NB, SCAN_T>>>();
    k_scan3<<<SCAN_NB, SCAN_T>>>();
    k_fill<<<gE8, 256>>>(ei);

    gemm_tf32<float><<<gB, 256>>>(x, W1, hs, dis, M);
    aggregate_s<<<gAg, 256>>>(hs, b1, x1);
    gemm_tf32<__half><<<gB, 256>>>(x1, W2, hs, dis, M);
    aggregate_s<<<gAg, 256>>>(hs, b2, x2);
    gemm_out_tf32<<<gBo, 256>>>(x1, x2, Wo, bo, out, M);
}

// round 13
// speedup vs baseline: 1.4870x; 1.4870x over previous
#include <cuda_runtime.h>
#include <cuda_fp16.h>
#include <mma.h>
#include <math.h>

using namespace nvcuda;

#define N_NODES 100000
#define N_PAD   100096
#define N_EDGES 1600000
#define CHN 128
#define OUTCH 64
#define SCAN_T 512
#define SCAN_NB ((N_NODES + SCAN_T - 1) / SCAN_T)   // 196

// ---------------- device scratch ------------------------------------------
__device__ int    g_is64;
__device__ int    g_cnt[N_NODES];
__device__ int    g_row[N_NODES + 1];
__device__ int    g_cur[N_NODES];
__device__ float  g_dis[N_NODES];
__device__ int    g_csr[N_EDGES];
__device__ int    g_bsum[SCAN_NB];
__device__ int    g_boff[SCAN_NB];
__device__ __half g_hs[N_PAD * CHN];
__device__ __half g_x1[N_PAD * CHN];
__device__ __half g_x2[N_PAD * CHN];

// ---------------- init: zero counters + dtype sniff ------------------------
__global__ void k_init(const void* __restrict__ edges) {
    int i = blockIdx.x * blockDim.x + threadIdx.x;
    if (i < N_NODES) g_cnt[i] = 0;
    if (blockIdx.x == 0) {
        __shared__ int cnt;
        if (threadIdx.x == 0) cnt = 0;
        __syncthreads();
        const int* p = (const int*)edges;
        int z = 0;
#pragma unroll
        for (int u = 0; u < 4; u++) {
            int w = (threadIdx.x * 4 + u) * 2 + 1;
            z += (p[w] == 0);
        }
        atomicAdd(&cnt, z);
        __syncthreads();
        if (threadIdx.x == 0) g_is64 = (cnt > 512) ? 1 : 0;
    }
}

__global__ void k_hist(const void* __restrict__ edges) {
    int base = (blockIdx.x * blockDim.x + threadIdx.x) * 8;
    int is64 = g_is64;
#pragma unroll
    for (int u = 0; u < 8; u++) {
        int i = base + u;
        if (i >= N_EDGES) break;
        int d;
        if (is64) d = (int)((const long long*)edges)[N_EDGES + i];
        else      d = ((const int*)edges)[N_EDGES + i];
        atomicAdd(&g_cnt[d], 1);
    }
}

// ---------------- 3-phase parallel scan ------------------------------------
__global__ void k_scan1() {
    __shared__ int s[SCAN_T];
    int i = blockIdx.x * SCAN_T + threadIdx.x;
    int v = (i < N_NODES) ? g_cnt[i] : 0;
    s[threadIdx.x] = v;
    __syncthreads();
    for (int off = SCAN_T / 2; off > 0; off >>= 1) {
        if (threadIdx.x < off) s[threadIdx.x] += s[threadIdx.x + off];
        __syncthreads();
    }
    if (threadIdx.x == 0) g_bsum[blockIdx.x] = s[0];
}

__global__ void k_scan2() {
    __shared__ int s[256];
    int t = threadIdx.x;
    int v = (t < SCAN_NB) ? g_bsum[t] : 0;
    s[t] = v;
    __syncthreads();
    for (int off = 1; off < 256; off <<= 1) {
        int u = (t >= off) ? s[t - off] : 0;
        __syncthreads();
        s[t] += u;
        __syncthreads();
    }
    if (t < SCAN_NB) g_boff[t] = s[t] - v;
}

__global__ void k_scan3() {
    __shared__ int s[SCAN_T];
    int t = threadIdx.x;
    int i = blockIdx.x * SCAN_T + t;
    int c = (i < N_NODES) ? g_cnt[i] : 0;
    s[t] = c;
    __syncthreads();
    for (int off = 1; off < SCAN_T; off <<= 1) {
        int u = (t >= off) ? s[t - off] : 0;
        __syncthreads();
        s[t] += u;
        __syncthreads();
    }
    if (i < N_NODES) {
        int excl = g_boff[blockIdx.x] + s[t] - c;
        g_row[i] = excl;
        g_cur[i] = excl;
        g_dis[i] = rsqrtf((float)(c + 1));
        if (i == N_NODES - 1) g_row[N_NODES] = excl + c;
    }
}

__global__ void k_fill(const void* __restrict__ edges) {
    int base = (blockIdx.x * blockDim.x + threadIdx.x) * 8;
    int is64 = g_is64;
#pragma unroll
    for (int u = 0; u < 8; u++) {
        int i = base + u;
        if (i >= N_EDGES) break;
        int sN, dN;
        if (is64) {
            const long long* p = (const long long*)edges;
            sN = (int)p[i]; dN = (int)p[N_EDGES + i];
        } else {
            const int* p = (const int*)edges;
            sN = p[i]; dN = p[N_EDGES + i];
        }
        int idx = atomicAdd(&g_cur[dN], 1);
        g_csr[idx] = sN;
    }
}

// ---------------- fp16 HMMA GEMM: A[M,128] @ B[128,128] -------------------
// Same 192x128 tile / warp layout as the R7/R11 tf32 version; half smem,
// m16n16k16 fragments, fp32 accumulate. Epilogue: *dis[r], emit fp16.
#define AS_HALF (192 * 40)
#define BS_HALF (32 * 136)

template <typename AT>
__global__ __launch_bounds__(256) void gemm_h(
    const AT* __restrict__ A, const float* __restrict__ B,
    __half* __restrict__ out, const float* __restrict__ dis, int M)
{
    __shared__ __half pool[AS_HALF + BS_HALF];           // 24448 B
    __half (*As)[40]  = (__half(*)[40])pool;
    __half (*Bs)[136] = (__half(*)[136])(pool + AS_HALF);
    float (*stage)[16][20] = (float(*)[16][20])pool;     // aliases (10240 B)

    int tid = threadIdx.x;
    int wid = tid >> 5;
    int lane = tid & 31;
    int wm = wid & 3;
    int wn = wid >> 2;
    int bm = blockIdx.x * 192;

    wmma::fragment<wmma::accumulator, 16, 16, 16, float> acc[3][4];
#pragma unroll
    for (int i = 0; i < 3; i++)
#pragma unroll
        for (int j = 0; j < 4; j++) wmma::fill_fragment(acc[i][j], 0.f);

    for (int k0 = 0; k0 < 128; k0 += 32) {
        // A tile: 192x32 elements, 4 per thread per iter, 6 iters
#pragma unroll
        for (int h = 0; h < 6; h++) {
            int i4 = tid + h * 256;
            int r = i4 >> 3, c = (i4 & 7) * 4;
            __half2 p0, p1;
            if (bm + r < M) {
                if constexpr (sizeof(AT) == 4) {
                    float4 v = *(const float4*)((const float*)A + (long)(bm + r) * 128 + k0 + c);
                    p0 = __float22half2_rn(make_float2(v.x, v.y));
                    p1 = __float22half2_rn(make_float2(v.z, v.w));
                } else {
                    uint2 raw = *(const uint2*)((const __half*)A + (long)(bm + r) * 128 + k0 + c);
                    p0 = *(__half2*)&raw.x;
                    p1 = *(__half2*)&raw.y;
                }
            } else {
                p0 = __half2half2(__float2half(0.f));
                p1 = p0;
            }
            *(__half2*)&As[r][c]     = p0;
            *(__half2*)&As[r][c + 2] = p1;
        }
        // B tile: 32x128 elements, fp32 -> half
#pragma unroll
        for (int h = 0; h < 4; h++) {
            int i4 = tid + h * 256;
            int r = i4 >> 5, c = (i4 & 31) * 4;
            float4 v = *(const float4*)(B + (long)(k0 + r) * 128 + c);
            *(__half2*)&Bs[r][c]     = __float22half2_rn(make_float2(v.x, v.y));
            *(__half2*)&Bs[r][c + 2] = __float22half2_rn(make_float2(v.z, v.w));
        }
        __syncthreads();
#pragma unroll
        for (int kk = 0; kk < 2; kk++) {
            wmma::fragment<wmma::matrix_a, 16, 16, 16, __half, wmma::row_major> af[3];
            wmma::fragment<wmma::matrix_b, 16, 16, 16, __half, wmma::row_major> bf[4];
#pragma unroll
            for (int i = 0; i < 3; i++)
                wmma::load_matrix_sync(af[i], &As[wm * 48 + i * 16][kk * 16], 40);
#pragma unroll
            for (int j = 0; j < 4; j++)
                wmma::load_matrix_sync(bf[j], &Bs[kk * 16][wn * 64 + j * 16], 136);
#pragma unroll
            for (int i = 0; i < 3; i++)
#pragma unroll
                for (int j = 0; j < 4; j++)
                    wmma::mma_sync(acc[i][j], af[i], bf[j], acc[i][j]);
        }
        __syncthreads();
    }
#pragma unroll
    for (int i = 0; i < 3; i++)
#pragma unroll
        for (int j = 0; j < 4; j++) {
            wmma::store_matrix_sync(&stage[wid][0][0], acc[i][j], 20, wmma::mem_row_major);
            __syncwarp();
            int r = bm + wm * 48 + i * 16 + (lane >> 1);
            float dsc = (r < M) ? dis[r] : 0.f;
            const float* srow = &stage[wid][lane >> 1][(lane & 1) * 8];
            __half2 h0 = __float22half2_rn(make_float2(srow[0] * dsc, srow[1] * dsc));
            __half2 h1 = __float22half2_rn(make_float2(srow[2] * dsc, srow[3] * dsc));
            __half2 h2 = __float22half2_rn(make_float2(srow[4] * dsc, srow[5] * dsc));
            __half2 h3 = __float22half2_rn(make_float2(srow[6] * dsc, srow[7] * dsc));
            uint4 pack;
            pack.x = *(unsigned*)&h0;
            pack.y = *(unsigned*)&h1;
            pack.z = *(unsigned*)&h2;
            pack.w = *(unsigned*)&h3;
            *(uint4*)(out + (long)r * 128 + wn * 64 + j * 16 + (lane & 1) * 8) = pack;
            __syncwarp();
        }
}

// ---------------- fp16 output GEMM: (x1+x2)[M,128] @ Wo[128,64] + bo ------
__global__ __launch_bounds__(256) void gemm_out_h(
    const __half* __restrict__ A1, const __half* __restrict__ A2,
    const float* __restrict__ B, const float* __restrict__ bias,
    float* __restrict__ out, int M)
{
    __shared__ __half As[128][40];
    __shared__ __half Bs[32][72];
    __shared__ float  Bt[16][72];
    int tid = threadIdx.x;
    int wid = tid >> 5;
    int bm = blockIdx.x * 128;

    for (int i = tid; i < 16 * 64; i += 256) Bt[i >> 6][i & 63] = bias[i & 63];
    __syncthreads();

    wmma::fragment<wmma::accumulator, 16, 16, 16, float> acc[4];
#pragma unroll
    for (int j = 0; j < 4; j++)
        wmma::load_matrix_sync(acc[j], &Bt[0][j * 16], 72, wmma::mem_row_major);

    for (int k0 = 0; k0 < 128; k0 += 32) {
#pragma unroll
        for (int h = 0; h < 4; h++) {
            int i4 = tid + h * 256;
            int r = i4 >> 3, c = (i4 & 7) * 4;
            __half2 p0, p1;
            if (bm + r < M) {
                uint2 r1 = *(const uint2*)(A1 + (long)(bm + r) * 128 + k0 + c);
                uint2 r2 = *(const uint2*)(A2 + (long)(bm + r) * 128 + k0 + c);
                p0 = __hadd2(*(__half2*)&r1.x, *(__half2*)&r2.x);
                p1 = __hadd2(*(__half2*)&r1.y, *(__half2*)&r2.y);
            } else {
                p0 = __half2half2(__float2half(0.f));
                p1 = p0;
            }
            *(__half2*)&As[r][c]     = p0;
            *(__half2*)&As[r][c + 2] = p1;
        }
        {
            int r = tid >> 4, c = (tid & 15) * 4;
            float4 v = *(const float4*)(B + (long)(k0 + r) * 64 + c);
            *(__half2*)&Bs[r][c]     = __float22half2_rn(make_float2(v.x, v.y));
            *(__half2*)&Bs[r][c + 2] = __float22half2_rn(make_float2(v.z, v.w));
            r = (tid + 256) >> 4; c = ((tid + 256) & 15) * 4;
            v = *(const float4*)(B + (long)(k0 + r) * 64 + c);
            *(__half2*)&Bs[r][c]     = __float22half2_rn(make_float2(v.x, v.y));
            *(__half2*)&Bs[r][c + 2] = __float22half2_rn(make_float2(v.z, v.w));
        }
        __syncthreads();
#pragma unroll
        for (int kk = 0; kk < 2; kk++) {
            wmma::fragment<wmma::matrix_a, 16, 16, 16, __half, wmma::row_major> af;
            wmma::fragment<wmma::matrix_b, 16, 16, 16, __half, wmma::row_major> bf[4];
            wmma::load_matrix_sync(af, &As[wid * 16][kk * 16], 40);
#pragma unroll
            for (int j = 0; j < 4; j++)
                wmma::load_matrix_sync(bf[j], &Bs[kk * 16][j * 16], 72);
#pragma unroll
            for (int j = 0; j < 4; j++)
                wmma::mma_sync(acc[j], af, bf[j], acc[j]);
        }
        __syncthreads();
    }
    int r = bm + wid * 16;
    if (r + 16 <= M) {
#pragma unroll
        for (int j = 0; j < 4; j++)
            wmma::store_matrix_sync(out + (long)r * 64 + j * 16,
                                    acc[j], 64, wmma::mem_row_major);
    }
}

// ---------------- aggregation (R11): warp/node, 8-wide + scalar tail ------
__device__ __forceinline__ float4 gather_h(const __half* hs, int s, int lane) {
    uint2 raw = *(const uint2*)(hs + (long)s * 128 + lane * 4);
    float2 a = __half22float2(*(__half2*)&raw.x);
    float2 b = __half22float2(*(__half2*)&raw.y);
    return make_float4(a.x, a.y, b.x, b.y);
}

__global__ __launch_bounds__(256) void aggregate_s(
    const __half* __restrict__ hs, const float* __restrict__ bias,
    __half* __restrict__ xo)
{
    int gw = (blockIdx.x * blockDim.x + threadIdx.x) >> 5;
    int lane = threadIdx.x & 31;
    if (gw >= N_NODES) return;
    int beg = g_row[gw];
    int end = g_row[gw + 1];
    float4 acc = gather_h(hs, gw, lane);   // self term, pre-scaled
    int e = beg;
    for (; e + 8 <= end; e += 8) {
        int s0 = g_csr[e],     s1 = g_csr[e + 1], s2 = g_csr[e + 2], s3 = g_csr[e + 3];
        int s4 = g_csr[e + 4], s5 = g_csr[e + 5], s6 = g_csr[e + 6], s7 = g_csr[e + 7];
        float4 v0 = gather_h(hs, s0, lane);
        float4 v1 = gather_h(hs, s1, lane);
        float4 v2 = gather_h(hs, s2, lane);
        float4 v3 = gather_h(hs, s3, lane);
        float4 v4 = gather_h(hs, s4, lane);
        float4 v5 = gather_h(hs, s5, lane);
        float4 v6 = gather_h(hs, s6, lane);
        float4 v7 = gather_h(hs, s7, lane);
        acc.x += (v0.x + v1.x) + (v2.x + v3.x) + (v4.x + v5.x) + (v6.x + v7.x);
        acc.y += (v0.y + v1.y) + (v2.y + v3.y) + (v4.y + v5.y) + (v6.y + v7.y);
        acc.z += (v0.z + v1.z) + (v2.z + v3.z) + (v4.z + v5.z) + (v6.z + v7.z);
        acc.w += (v0.w + v1.w) + (v2.w + v3.w) + (v4.w + v5.w) + (v6.w + v7.w);
    }
    for (; e < end; e++) {
        float4 v = gather_h(hs, g_csr[e], lane);
        acc.x += v.x; acc.y += v.y; acc.z += v.z; acc.w += v.w;
    }
    float dd = g_dis[gw];
    float4 b = *(const float4*)(bias + lane * 4);
    __half2 o0 = __float22half2_rn(make_float2(
        fmaxf(acc.x * dd + b.x, 0.f), fmaxf(acc.y * dd + b.y, 0.f)));
    __half2 o1 = __float22half2_rn(make_float2(
        fmaxf(acc.z * dd + b.z, 0.f), fmaxf(acc.w * dd + b.w, 0.f)));
    uint2 pack;
    pack.x = *(unsigned*)&o0;
    pack.y = *(unsigned*)&o1;
    *(uint2*)(xo + (long)gw * 128 + lane * 4) = pack;
}

// ---------------- launch ---------------------------------------------------
extern "C" void kernel_launch(void* const* d_in, const int* in_sizes, int n_in,
                              void* d_out, int out_size)
{
    const float* x  = (const float*)d_in[0];
    const void*  ei = d_in[1];
    const float* W1 = (const float*)d_in[2];
    const float* b1 = (const float*)d_in[3];
    const float* W2 = (const float*)d_in[4];
    const float* b2 = (const float*)d_in[5];
    const float* Wo = (const float*)d_in[6];
    const float* bo = (const float*)d_in[7];
    float* out = (float*)d_out;

    __half *hs, *x1, *x2;
    float* dis;
    cudaGetSymbolAddress((void**)&hs,  g_hs);
    cudaGetSymbolAddress((void**)&x1,  g_x1);
    cudaGetSymbolAddress((void**)&x2,  g_x2);
    cudaGetSymbolAddress((void**)&dis, g_dis);

    const int M = N_NODES;
    int gB  = (M + 191) / 192;
    int gBo = (M + 127) / 128;
    int gN  = (M + 255) / 256;
    int gE8 = (N_EDGES + 2047) / 2048;
    int gAg = (M * 32 + 255) / 256;

    k_init<<<gN, 256>>>(ei);
    k_hist<<<gE8, 256>>>(ei);
    k_scan1<<<SCAN_NB, SCAN_T>>>();
    k_scan2<<<1, 256>>>();
    k_scan3<<<SCAN_NB, SCAN_T>>>();
    k_fill<<<gE8, 256>>>(ei);

    gemm_h<float><<<gB, 256>>>(x, W1, hs, dis, M);
    aggregate_s<<<gAg, 256>>>(hs, b1, x1);
    gemm_h<__half><<<gB, 256>>>(x1, W2, hs, dis, M);
    aggregate_s<<<gAg, 256>>>(hs, b2, x2);
    gemm_out_h<<<gBo, 256>>>(x1, x2, Wo, bo, out, M);
}

// round 14
// speedup vs baseline: 1.5059x; 1.0127x over previous
#include <cuda_runtime.h>
#include <cuda_fp16.h>
#include <mma.h>
#include <math.h>

using namespace nvcuda;

#define N_NODES 100000
#define N_PAD   100096
#define N_EDGES 1600000
#define CHN 128
#define OUTCH 64
#define SCAN_T 512
#define SCAN_NB ((N_NODES + SCAN_T - 1) / SCAN_T)   // 196

// ---------------- device scratch ------------------------------------------
__device__ int    g_is64;
__device__ int    g_cnt[N_NODES];        // statically 0; re-zeroed by k_scan3
__device__ int    g_row[N_NODES + 1];
__device__ int    g_cur[N_NODES];
__device__ float  g_dis[N_NODES];
__device__ int    g_csr[N_EDGES];
__device__ int    g_bsum[SCAN_NB];
__device__ __half g_hs[N_PAD * CHN];
__device__ __half g_x1[N_PAD * CHN];
__device__ __half g_x2[N_PAD * CHN];

// ---------------- dtype sniff (1 block) ------------------------------------
__global__ void k_init(const void* __restrict__ edges) {
    __shared__ int cnt;
    if (threadIdx.x == 0) cnt = 0;
    __syncthreads();
    const int* p = (const int*)edges;
    int z = 0;
#pragma unroll
    for (int u = 0; u < 4; u++) {
        int w = (threadIdx.x * 4 + u) * 2 + 1;
        z += (p[w] == 0);
    }
    atomicAdd(&cnt, z);
    __syncthreads();
    if (threadIdx.x == 0) g_is64 = (cnt > 512) ? 1 : 0;
}

__global__ void k_hist(const void* __restrict__ edges) {
    int base = (blockIdx.x * blockDim.x + threadIdx.x) * 8;
    int is64 = g_is64;
#pragma unroll
    for (int u = 0; u < 8; u++) {
        int i = base + u;
        if (i >= N_EDGES) break;
        int d;
        if (is64) d = (int)((const long long*)edges)[N_EDGES + i];
        else      d = ((const int*)edges)[N_EDGES + i];
        atomicAdd(&g_cnt[d], 1);
    }
}

// ---------------- 2-kernel scan --------------------------------------------
__global__ void k_scan1() {
    __shared__ int s[SCAN_T];
    int i = blockIdx.x * SCAN_T + threadIdx.x;
    int v = (i < N_NODES) ? g_cnt[i] : 0;
    s[threadIdx.x] = v;
    __syncthreads();
    for (int off = SCAN_T / 2; off > 0; off >>= 1) {
        if (threadIdx.x < off) s[threadIdx.x] += s[threadIdx.x + off];
        __syncthreads();
    }
    if (threadIdx.x == 0) g_bsum[blockIdx.x] = s[0];
}

// Each block redundantly scans the 196 block sums (drops k_scan2),
// emits row/cur/dis, zeroes g_cnt for the next replay.
__global__ void k_scan3() {
    __shared__ int s[SCAN_T];
    __shared__ int bs[256];
    int t = threadIdx.x;
    if (t < 256) bs[t] = (t < SCAN_NB) ? g_bsum[t] : 0;
    __syncthreads();
    for (int off = 1; off < 256; off <<= 1) {
        int u = (t >= off && t < 256) ? bs[t - off] : 0;
        __syncthreads();
        if (t < 256) bs[t] += u;
        __syncthreads();
    }
    int boff = (blockIdx.x > 0) ? bs[blockIdx.x - 1] : 0;
    __syncthreads();

    int i = blockIdx.x * SCAN_T + t;
    int c = (i < N_NODES) ? g_cnt[i] : 0;
    s[t] = c;
    __syncthreads();
    for (int off = 1; off < SCAN_T; off <<= 1) {
        int u = (t >= off) ? s[t - off] : 0;
        __syncthreads();
        s[t] += u;
        __syncthreads();
    }
    if (i < N_NODES) {
        int excl = boff + s[t] - c;
        g_row[i] = excl;
        g_cur[i] = excl;
        g_dis[i] = rsqrtf((float)(c + 1));
        g_cnt[i] = 0;                      // restore invariant for next replay
        if (i == N_NODES - 1) g_row[N_NODES] = excl + c;
    }
}

__global__ void k_fill(const void* __restrict__ edges) {
    int base = (blockIdx.x * blockDim.x + threadIdx.x) * 8;
    int is64 = g_is64;
#pragma unroll
    for (int u = 0; u < 8; u++) {
        int i = base + u;
        if (i >= N_EDGES) break;
        int sN, dN;
        if (is64) {
            const long long* p = (const long long*)edges;
            sN = (int)p[i]; dN = (int)p[N_EDGES + i];
        } else {
            const int* p = (const int*)edges;
            sN = p[i]; dN = p[N_EDGES + i];
        }
        int idx = atomicAdd(&g_cur[dN], 1);
        g_csr[idx] = sN;
    }
}

// ---------------- fp16 HMMA GEMM, K-chunk 64 ------------------------------
// A[M,128] @ B[128,128]; 192x128 tile; epilogue *dis[r], fp16 out.
template <typename AT>
__global__ __launch_bounds__(256) void gemm_h(
    const AT* __restrict__ A, const float* __restrict__ B,
    __half* __restrict__ out, const float* __restrict__ dis, int M)
{
    __shared__ __half As[192][72];       // 27648 B
    __shared__ __half Bs[64][136];       // 17408 B
    float (*stage)[16][20] = (float(*)[16][20])&As[0][0];   // aliases (10240 B)

    int tid = threadIdx.x;
    int wid = tid >> 5;
    int lane = tid & 31;
    int wm = wid & 3;
    int wn = wid >> 2;
    int bm = blockIdx.x * 192;

    wmma::fragment<wmma::accumulator, 16, 16, 16, float> acc[3][4];
#pragma unroll
    for (int i = 0; i < 3; i++)
#pragma unroll
        for (int j = 0; j < 4; j++) wmma::fill_fragment(acc[i][j], 0.f);

    for (int k0 = 0; k0 < 128; k0 += 64) {
        // A tile: 192x64 elements, 4 per thread, 12 iters
#pragma unroll
        for (int h = 0; h < 12; h++) {
            int i4 = tid + h * 256;
            int r = i4 >> 4, c = (i4 & 15) * 4;
            __half2 p0, p1;
            if (bm + r < M) {
                if constexpr (sizeof(AT) == 4) {
                    float4 v = *(const float4*)((const float*)A + (long)(bm + r) * 128 + k0 + c);
                    p0 = __float22half2_rn(make_float2(v.x, v.y));
                    p1 = __float22half2_rn(make_float2(v.z, v.w));
                } else {
                    uint2 raw = *(const uint2*)((const __half*)A + (long)(bm + r) * 128 + k0 + c);
                    p0 = *(__half2*)&raw.x;
                    p1 = *(__half2*)&raw.y;
                }
            } else {
                p0 = __half2half2(__float2half(0.f));
                p1 = p0;
            }
            *(__half2*)&As[r][c]     = p0;
            *(__half2*)&As[r][c + 2] = p1;
        }
        // B tile: 64x128 fp32 -> half, 8 iters
#pragma unroll
        for (int h = 0; h < 8; h++) {
            int i4 = tid + h * 256;
            int r = i4 >> 5, c = (i4 & 31) * 4;
            float4 v = *(const float4*)(B + (long)(k0 + r) * 128 + c);
            *(__half2*)&Bs[r][c]     = __float22half2_rn(make_float2(v.x, v.y));
            *(__half2*)&Bs[r][c + 2] = __float22half2_rn(make_float2(v.z, v.w));
        }
        __syncthreads();
#pragma unroll
        for (int kk = 0; kk < 4; kk++) {
            wmma::fragment<wmma::matrix_a, 16, 16, 16, __half, wmma::row_major> af[3];
            wmma::fragment<wmma::matrix_b, 16, 16, 16, __half, wmma::row_major> bf[4];
#pragma unroll
            for (int i = 0; i < 3; i++)
                wmma::load_matrix_sync(af[i], &As[wm * 48 + i * 16][kk * 16], 72);
#pragma unroll
            for (int j = 0; j < 4; j++)
                wmma::load_matrix_sync(bf[j], &Bs[kk * 16][wn * 64 + j * 16], 136);
#pragma unroll
            for (int i = 0; i < 3; i++)
#pragma unroll
                for (int j = 0; j < 4; j++)
                    wmma::mma_sync(acc[i][j], af[i], bf[j], acc[i][j]);
        }
        __syncthreads();
    }
#pragma unroll
    for (int i = 0; i < 3; i++)
#pragma unroll
        for (int j = 0; j < 4; j++) {
            wmma::store_matrix_sync(&stage[wid][0][0], acc[i][j], 20, wmma::mem_row_major);
            __syncwarp();
            int r = bm + wm * 48 + i * 16 + (lane >> 1);
            float dsc = (r < M) ? dis[r] : 0.f;
            const float* srow = &stage[wid][lane >> 1][(lane & 1) * 8];
            __half2 h0 = __float22half2_rn(make_float2(srow[0] * dsc, srow[1] * dsc));
            __half2 h1 = __float22half2_rn(make_float2(srow[2] * dsc, srow[3] * dsc));
            __half2 h2 = __float22half2_rn(make_float2(srow[4] * dsc, srow[5] * dsc));
            __half2 h3 = __float22half2_rn(make_float2(srow[6] * dsc, srow[7] * dsc));
            uint4 pack;
            pack.x = *(unsigned*)&h0;
            pack.y = *(unsigned*)&h1;
            pack.z = *(unsigned*)&h2;
            pack.w = *(unsigned*)&h3;
            *(uint4*)(out + (long)r * 128 + wn * 64 + j * 16 + (lane & 1) * 8) = pack;
            __syncwarp();
        }
}

// ---------------- fp16 output GEMM, K-chunk 64 ----------------------------
__global__ __launch_bounds__(256) void gemm_out_h(
    const __half* __restrict__ A1, const __half* __restrict__ A2,
    const float* __restrict__ B, const float* __restrict__ bias,
    float* __restrict__ out, int M)
{
    __shared__ __half As[128][72];       // 18432 B
    __shared__ __half Bs[64][72];        // 9216 B
    __shared__ float  Bt[16][72];        // 4608 B
    int tid = threadIdx.x;
    int wid = tid >> 5;
    int bm = blockIdx.x * 128;

    for (int i = tid; i < 16 * 64; i += 256) Bt[i >> 6][i & 63] = bias[i & 63];
    __syncthreads();

    wmma::fragment<wmma::accumulator, 16, 16, 16, float> acc[4];
#pragma unroll
    for (int j = 0; j < 4; j++)
        wmma::load_matrix_sync(acc[j], &Bt[0][j * 16], 72, wmma::mem_row_major);

    for (int k0 = 0; k0 < 128; k0 += 64) {
        // A: 128x64 elements, 8 iters
#pragma unroll
        for (int h = 0; h < 8; h++) {
            int i4 = tid + h * 256;
            int r = i4 >> 4, c = (i4 & 15) * 4;
            __half2 p0, p1;
            if (bm + r < M) {
                uint2 r1 = *(const uint2*)(A1 + (long)(bm + r) * 128 + k0 + c);
                uint2 r2 = *(const uint2*)(A2 + (long)(bm + r) * 128 + k0 + c);
                p0 = __hadd2(*(__half2*)&r1.x, *(__half2*)&r2.x);
                p1 = __hadd2(*(__half2*)&r1.y, *(__half2*)&r2.y);
            } else {
                p0 = __half2half2(__float2half(0.f));
                p1 = p0;
            }
            *(__half2*)&As[r][c]     = p0;
            *(__half2*)&As[r][c + 2] = p1;
        }
        // B: 64x64 fp32 -> half, 4 iters
#pragma unroll
        for (int h = 0; h < 4; h++) {
            int i4 = tid + h * 256;
            int r = i4 >> 4, c = (i4 & 15) * 4;
            float4 v = *(const float4*)(B + (long)(k0 + r) * 64 + c);
            *(__half2*)&Bs[r][c]     = __float22half2_rn(make_float2(v.x, v.y));
            *(__half2*)&Bs[r][c + 2] = __float22half2_rn(make_float2(v.z, v.w));
        }
        __syncthreads();
#pragma unroll
        for (int kk = 0; kk < 4; kk++) {
            wmma::fragment<wmma::matrix_a, 16, 16, 16, __half, wmma::row_major> af;
            wmma::fragment<wmma::matrix_b, 16, 16, 16, __half, wmma::row_major> bf[4];
            wmma::load_matrix_sync(af, &As[wid * 16][kk * 16], 72);
#pragma unroll
            for (int j = 0; j < 4; j++)
                wmma::load_matrix_sync(bf[j], &Bs[kk * 16][j * 16], 72);
#pragma unroll
            for (int j = 0; j < 4; j++)
                wmma::mma_sync(acc[j], af, bf[j], acc[j]);
        }
        __syncthreads();
    }
    int r = bm + wid * 16;
    if (r + 16 <= M) {
#pragma unroll
        for (int j = 0; j < 4; j++)
            wmma::store_matrix_sync(out + (long)r * 64 + j * 16,
                                    acc[j], 64, wmma::mem_row_major);
    }
}

// ---------------- aggregation (R11/R13): warp/node, 8-wide + tail ---------
__device__ __forceinline__ float4 gather_h(const __half* hs, int s, int lane) {
    uint2 raw = *(const uint2*)(hs + (long)s * 128 + lane * 4);
    float2 a = __half22float2(*(__half2*)&raw.x);
    float2 b = __half22float2(*(__half2*)&raw.y);
    return make_float4(a.x, a.y, b.x, b.y);
}

__global__ __launch_bounds__(256) void aggregate_s(
    const __half* __restrict__ hs, const float* __restrict__ bias,
    __half* __restrict__ xo)
{
    int gw = (blockIdx.x * blockDim.x + threadIdx.x) >> 5;
    int lane = threadIdx.x & 31;
    if (gw >= N_NODES) return;
    int beg = g_row[gw];
    int end = g_row[gw + 1];
    float4 acc = gather_h(hs, gw, lane);   // self term, pre-scaled
    int e = beg;
    for (; e + 8 <= end; e += 8) {
        int s0 = g_csr[e],     s1 = g_csr[e + 1], s2 = g_csr[e + 2], s3 = g_csr[e + 3];
        int s4 = g_csr[e + 4], s5 = g_csr[e + 5], s6 = g_csr[e + 6], s7 = g_csr[e + 7];
        float4 v0 = gather_h(hs, s0, lane);
        float4 v1 = gather_h(hs, s1, lane);
        float4 v2 = gather_h(hs, s2, lane);
        float4 v3 = gather_h(hs, s3, lane);
        float4 v4 = gather_h(hs, s4, lane);
        float4 v5 = gather_h(hs, s5, lane);
        float4 v6 = gather_h(hs, s6, lane);
        float4 v7 = gather_h(hs, s7, lane);
        acc.x += (v0.x + v1.x) + (v2.x + v3.x) + (v4.x + v5.x) + (v6.x + v7.x);
        acc.y += (v0.y + v1.y) + (v2.y + v3.y) + (v4.y + v5.y) + (v6.y + v7.y);
        acc.z += (v0.z + v1.z) + (v2.z + v3.z) + (v4.z + v5.z) + (v6.z + v7.z);
        acc.w += (v0.w + v1.w) + (v2.w + v3.w) + (v4.w + v5.w) + (v6.w + v7.w);
    }
    for (; e < end; e++) {
        float4 v = gather_h(hs, g_csr[e], lane);
        acc.x += v.x; acc.y += v.y; acc.z += v.z; acc.w += v.w;
    }
    float dd = g_dis[gw];
    float4 b = *(const float4*)(bias + lane * 4);
    __half2 o0 = __float22half2_rn(make_float2(
        fmaxf(acc.x * dd + b.x, 0.f), fmaxf(acc.y * dd + b.y, 0.f)));
    __half2 o1 = __float22half2_rn(make_float2(
        fmaxf(acc.z * dd + b.z, 0.f), fmaxf(acc.w * dd + b.w, 0.f)));
    uint2 pack;
    pack.x = *(unsigned*)&o0;
    pack.y = *(unsigned*)&o1;
    *(uint2*)(xo + (long)gw * 128 + lane * 4) = pack;
}

// ---------------- launch ---------------------------------------------------
extern "C" void kernel_launch(void* const* d_in, const int* in_sizes, int n_in,
                              void* d_out, int out_size)
{
    const float* x  = (const float*)d_in[0];
    const void*  ei = d_in[1];
    const float* W1 = (const float*)d_in[2];
    const float* b1 = (const float*)d_in[3];
    const float* W2 = (const float*)d_in[4];
    const float* b2 = (const float*)d_in[5];
    const float* Wo = (const float*)d_in[6];
    const float* bo = (const float*)d_in[7];
    float* out = (float*)d_out;

    __half *hs, *x1, *x2;
    float* dis;
    cudaGetSymbolAddress((void**)&hs,  g_hs);
    cudaGetSymbolAddress((void**)&x1,  g_x1);
    cudaGetSymbolAddress((void**)&x2,  g_x2);
    cudaGetSymbolAddress((void**)&dis, g_dis);

    const int M = N_NODES;
    int gB  = (M + 191) / 192;
    int gBo = (M + 127) / 128;
    int gE8 = (N_EDGES + 2047) / 2048;
    int gAg = (M * 32 + 255) / 256;

    k_init<<<1, 1024>>>(ei);
    k_hist<<<gE8, 256>>>(ei);
    k_scan1<<<SCAN_NB, SCAN_T>>>();
    k_scan3<<<SCAN_NB, SCAN_T>>>();
    k_fill<<<gE8, 256>>>(ei);

    gemm_h<float><<<gB, 256>>>(x, W1, hs, dis, M);
    aggregate_s<<<gAg, 256>>>(hs, b1, x1);
    gemm_h<__half><<<gB, 256>>>(x1, W2, hs, dis, M);
    aggregate_s<<<gAg, 256>>>(hs, b2, x2);
    gemm_out_h<<<gBo, 256>>>(x1, x2, Wo, bo, out, M);
}

// round 15
// speedup vs baseline: 1.6207x; 1.0763x over previous
#include <cuda_runtime.h>
#include <cuda_fp16.h>
#include <mma.h>
#include <math.h>

using namespace nvcuda;

#define N_NODES 100000
#define N_PAD   100096
#define N_EDGES 1600000
#define CHN 128
#define OUTCH 64
#define SCAN_T 512
#define SCAN_NB ((N_NODES + SCAN_T - 1) / SCAN_T)   // 196

// ---------------- device scratch ------------------------------------------
__device__ int    g_is64;
__device__ int    g_cnt[N_NODES];        // statically 0; re-zeroed by k_scan3
__device__ int    g_row[N_NODES + 1];
__device__ int    g_cur[N_NODES];
__device__ float  g_dis[N_NODES];
__device__ int    g_csr[N_EDGES];
__device__ int    g_bsum[SCAN_NB];
__device__ __half g_hs[N_PAD * CHN];
__device__ __half g_x1[N_PAD * CHN];
__device__ __half g_xs[N_PAD * CHN];     // layer2 emits x1 + x2 (fused)

// ---------------- dtype sniff (1 block) ------------------------------------
__global__ void k_init(const void* __restrict__ edges) {
    __shared__ int cnt;
    if (threadIdx.x == 0) cnt = 0;
    __syncthreads();
    const int* p = (const int*)edges;
    int z = 0;
#pragma unroll
    for (int u = 0; u < 4; u++) {
        int w = (threadIdx.x * 4 + u) * 2 + 1;
        z += (p[w] == 0);
    }
    atomicAdd(&cnt, z);
    __syncthreads();
    if (threadIdx.x == 0) g_is64 = (cnt > 512) ? 1 : 0;
}

__global__ void k_hist(const void* __restrict__ edges) {
    int base = (blockIdx.x * blockDim.x + threadIdx.x) * 8;
    int is64 = g_is64;
    if (base + 8 <= N_EDGES) {
        int d[8];
        if (is64) {
            const long long* p = (const long long*)edges + N_EDGES + base;
#pragma unroll
            for (int u = 0; u < 8; u++) d[u] = (int)p[u];
        } else {
            const int* p = (const int*)edges + N_EDGES + base;
#pragma unroll
            for (int u = 0; u < 8; u++) d[u] = p[u];
        }
#pragma unroll
        for (int u = 0; u < 8; u++) atomicAdd(&g_cnt[d[u]], 1);
    } else {
        for (int i = base; i < N_EDGES; i++) {
            int d;
            if (is64) d = (int)((const long long*)edges)[N_EDGES + i];
            else      d = ((const int*)edges)[N_EDGES + i];
            atomicAdd(&g_cnt[d], 1);
        }
    }
}

// ---------------- 2-kernel scan --------------------------------------------
__global__ void k_scan1() {
    __shared__ int s[SCAN_T];
    int i = blockIdx.x * SCAN_T + threadIdx.x;
    int v = (i < N_NODES) ? g_cnt[i] : 0;
    s[threadIdx.x] = v;
    __syncthreads();
    for (int off = SCAN_T / 2; off > 0; off >>= 1) {
        if (threadIdx.x < off) s[threadIdx.x] += s[threadIdx.x + off];
        __syncthreads();
    }
    if (threadIdx.x == 0) g_bsum[blockIdx.x] = s[0];
}

__global__ void k_scan3() {
    __shared__ int s[SCAN_T];
    __shared__ int bs[256];
    int t = threadIdx.x;
    if (t < 256) bs[t] = (t < SCAN_NB) ? g_bsum[t] : 0;
    __syncthreads();
    for (int off = 1; off < 256; off <<= 1) {
        int u = (t >= off && t < 256) ? bs[t - off] : 0;
        __syncthreads();
        if (t < 256) bs[t] += u;
        __syncthreads();
    }
    int boff = (blockIdx.x > 0) ? bs[blockIdx.x - 1] : 0;
    __syncthreads();

    int i = blockIdx.x * SCAN_T + t;
    int c = (i < N_NODES) ? g_cnt[i] : 0;
    s[t] = c;
    __syncthreads();
    for (int off = 1; off < SCAN_T; off <<= 1) {
        int u = (t >= off) ? s[t - off] : 0;
        __syncthreads();
        s[t] += u;
        __syncthreads();
    }
    if (i < N_NODES) {
        int excl = boff + s[t] - c;
        g_row[i] = excl;
        g_cur[i] = excl;
        g_dis[i] = rsqrtf((float)(c + 1));
        g_cnt[i] = 0;
        if (i == N_NODES - 1) g_row[N_NODES] = excl + c;
    }
}

__global__ void k_fill(const void* __restrict__ edges) {
    int base = (blockIdx.x * blockDim.x + threadIdx.x) * 8;
    int is64 = g_is64;
    if (base + 8 <= N_EDGES) {
        int sN[8], dN[8];
        if (is64) {
            const long long* ps = (const long long*)edges + base;
            const long long* pd = (const long long*)edges + N_EDGES + base;
#pragma unroll
            for (int u = 0; u < 8; u++) { sN[u] = (int)ps[u]; dN[u] = (int)pd[u]; }
        } else {
            const int* ps = (const int*)edges + base;
            const int* pd = (const int*)edges + N_EDGES + base;
#pragma unroll
            for (int u = 0; u < 8; u++) { sN[u] = ps[u]; dN[u] = pd[u]; }
        }
        int idx[8];
#pragma unroll
        for (int u = 0; u < 8; u++) idx[u] = atomicAdd(&g_cur[dN[u]], 1);
#pragma unroll
        for (int u = 0; u < 8; u++) g_csr[idx[u]] = sN[u];
    } else {
        for (int i = base; i < N_EDGES; i++) {
            int sN, dN;
            if (is64) {
                const long long* p = (const long long*)edges;
                sN = (int)p[i]; dN = (int)p[N_EDGES + i];
            } else {
                const int* p = (const int*)edges;
                sN = p[i]; dN = p[N_EDGES + i];
            }
            int idx = atomicAdd(&g_cur[dN], 1);
            g_csr[idx] = sN;
        }
    }
}

// ---------------- fp16 HMMA GEMM, 128-row tile, 2 blocks/SM ---------------
template <typename AT>
__global__ __launch_bounds__(256, 2) void gemm_h(
    const AT* __restrict__ A, const float* __restrict__ B,
    __half* __restrict__ out, const float* __restrict__ dis, int M)
{
    __shared__ __half As[128][72];       // 18432 B
    __shared__ __half Bs[64][136];       // 17408 B
    float (*stage)[16][20] = (float(*)[16][20])&As[0][0];   // aliases (10240 B)

    int tid = threadIdx.x;
    int wid = tid >> 5;
    int lane = tid & 31;
    int wm = wid & 3;                    // 4 row groups x 32 rows
    int wn = wid >> 2;                   // 2 col groups x 64 cols
    int bm = blockIdx.x * 128;

    wmma::fragment<wmma::accumulator, 16, 16, 16, float> acc[2][4];
#pragma unroll
    for (int i = 0; i < 2; i++)
#pragma unroll
        for (int j = 0; j < 4; j++) wmma::fill_fragment(acc[i][j], 0.f);

    for (int k0 = 0; k0 < 128; k0 += 64) {
        // A tile: 128x64 elements, 4/thread, 8 iters
#pragma unroll
        for (int h = 0; h < 8; h++) {
            int i4 = tid + h * 256;
            int r = i4 >> 4, c = (i4 & 15) * 4;
            __half2 p0, p1;
            if (bm + r < M) {
                if constexpr (sizeof(AT) == 4) {
                    float4 v = *(const float4*)((const float*)A + (long)(bm + r) * 128 + k0 + c);
                    p0 = __float22half2_rn(make_float2(v.x, v.y));
                    p1 = __float22half2_rn(make_float2(v.z, v.w));
                } else {
                    uint2 raw = *(const uint2*)((const __half*)A + (long)(bm + r) * 128 + k0 + c);
                    p0 = *(__half2*)&raw.x;
                    p1 = *(__half2*)&raw.y;
                }
            } else {
                p0 = __half2half2(__float2half(0.f));
                p1 = p0;
            }
            *(__half2*)&As[r][c]     = p0;
            *(__half2*)&As[r][c + 2] = p1;
        }
        // B tile: 64x128 fp32 -> half, 8 iters
#pragma unroll
        for (int h = 0; h < 8; h++) {
            int i4 = tid + h * 256;
            int r = i4 >> 5, c = (i4 & 31) * 4;
            float4 v = *(const float4*)(B + (long)(k0 + r) * 128 + c);
            *(__half2*)&Bs[r][c]     = __float22half2_rn(make_float2(v.x, v.y));
            *(__half2*)&Bs[r][c + 2] = __float22half2_rn(make_float2(v.z, v.w));
        }
        __syncthreads();
#pragma unroll
        for (int kk = 0; kk < 4; kk++) {
            wmma::fragment<wmma::matrix_a, 16, 16, 16, __half, wmma::row_major> af[2];
            wmma::fragment<wmma::matrix_b, 16, 16, 16, __half, wmma::row_major> bf[4];
#pragma unroll
            for (int i = 0; i < 2; i++)
                wmma::load_matrix_sync(af[i], &As[wm * 32 + i * 16][kk * 16], 72);
#pragma unroll
            for (int j = 0; j < 4; j++)
                wmma::load_matrix_sync(bf[j], &Bs[kk * 16][wn * 64 + j * 16], 136);
#pragma unroll
            for (int i = 0; i < 2; i++)
#pragma unroll
                for (int j = 0; j < 4; j++)
                    wmma::mma_sync(acc[i][j], af[i], bf[j], acc[i][j]);
        }
        __syncthreads();
    }
#pragma unroll
    for (int i = 0; i < 2; i++)
#pragma unroll
        for (int j = 0; j < 4; j++) {
            wmma::store_matrix_sync(&stage[wid][0][0], acc[i][j], 20, wmma::mem_row_major);
            __syncwarp();
            int r = bm + wm * 32 + i * 16 + (lane >> 1);
            float dsc = (r < M) ? dis[r] : 0.f;
            const float* srow = &stage[wid][lane >> 1][(lane & 1) * 8];
            __half2 h0 = __float22half2_rn(make_float2(srow[0] * dsc, srow[1] * dsc));
            __half2 h1 = __float22half2_rn(make_float2(srow[2] * dsc, srow[3] * dsc));
            __half2 h2 = __float22half2_rn(make_float2(srow[4] * dsc, srow[5] * dsc));
            __half2 h3 = __float22half2_rn(make_float2(srow[6] * dsc, srow[7] * dsc));
            uint4 pack;
            pack.x = *(unsigned*)&h0;
            pack.y = *(unsigned*)&h1;
            pack.z = *(unsigned*)&h2;
            pack.w = *(unsigned*)&h3;
            *(uint4*)(out + (long)r * 128 + wn * 64 + j * 16 + (lane & 1) * 8) = pack;
            __syncwarp();
        }
}

// ---------------- fp16 output GEMM: xs[M,128] @ Wo[128,64] + bo -----------
__global__ __launch_bounds__(256, 2) void gemm_out_h(
    const __half* __restrict__ A, const float* __restrict__ B,
    const float* __restrict__ bias, float* __restrict__ out, int M)
{
    __shared__ __half As[128][72];
    __shared__ __half Bs[64][72];
    __shared__ float  Bt[16][72];
    int tid = threadIdx.x;
    int wid = tid >> 5;
    int bm = blockIdx.x * 128;

    for (int i = tid; i < 16 * 64; i += 256) Bt[i >> 6][i & 63] = bias[i & 63];
    __syncthreads();

    wmma::fragment<wmma::accumulator, 16, 16, 16, float> acc[4];
#pragma unroll
    for (int j = 0; j < 4; j++)
        wmma::load_matrix_sync(acc[j], &Bt[0][j * 16], 72, wmma::mem_row_major);

    for (int k0 = 0; k0 < 128; k0 += 64) {
#pragma unroll
        for (int h = 0; h < 8; h++) {
            int i4 = tid + h * 256;
            int r = i4 >> 4, c = (i4 & 15) * 4;
            __half2 p0, p1;
            if (bm + r < M) {
                uint2 raw = *(const uint2*)(A + (long)(bm + r) * 128 + k0 + c);
                p0 = *(__half2*)&raw.x;
                p1 = *(__half2*)&raw.y;
            } else {
                p0 = __half2half2(__float2half(0.f));
                p1 = p0;
            }
            *(__half2*)&As[r][c]     = p0;
            *(__half2*)&As[r][c + 2] = p1;
        }
#pragma unroll
        for (int h = 0; h < 4; h++) {
            int i4 = tid + h * 256;
            int r = i4 >> 4, c = (i4 & 15) * 4;
            float4 v = *(const float4*)(B + (long)(k0 + r) * 64 + c);
            *(__half2*)&Bs[r][c]     = __float22half2_rn(make_float2(v.x, v.y));
            *(__half2*)&Bs[r][c + 2] = __float22half2_rn(make_float2(v.z, v.w));
        }
        __syncthreads();
#pragma unroll
        for (int kk = 0; kk < 4; kk++) {
            wmma::fragment<wmma::matrix_a, 16, 16, 16, __half, wmma::row_major> af;
            wmma::fragment<wmma::matrix_b, 16, 16, 16, __half, wmma::row_major> bf[4];
            wmma::load_matrix_sync(af, &As[wid * 16][kk * 16], 72);
#pragma unroll
            for (int j = 0; j < 4; j++)
                wmma::load_matrix_sync(bf[j], &Bs[kk * 16][j * 16], 72);
#pragma unroll
            for (int j = 0; j < 4; j++)
                wmma::mma_sync(acc[j], af, bf[j], acc[j]);
        }
        __syncthreads();
    }
    int r = bm + wid * 16;
    if (r + 16 <= M) {
#pragma unroll
        for (int j = 0; j < 4; j++)
            wmma::store_matrix_sync(out + (long)r * 64 + j * 16,
                                    acc[j], 64, wmma::mem_row_major);
    }
}

// ---------------- aggregation: warp/node, 8-wide; optional +prev fusion ---
__device__ __forceinline__ float4 gather_h(const __half* hs, int s, int lane) {
    uint2 raw = *(const uint2*)(hs + (long)s * 128 + lane * 4);
    float2 a = __half22float2(*(__half2*)&raw.x);
    float2 b = __half22float2(*(__half2*)&raw.y);
    return make_float4(a.x, a.y, b.x, b.y);
}

template <bool FUSE>
__global__ __launch_bounds__(256) void aggregate_s(
    const __half* __restrict__ hs, const float* __restrict__ bias,
    const __half* __restrict__ prev, __half* __restrict__ xo)
{
    int gw = (blockIdx.x * blockDim.x + threadIdx.x) >> 5;
    int lane = threadIdx.x & 31;
    if (gw >= N_NODES) return;
    int beg = g_row[gw];
    int end = g_row[gw + 1];
    float4 acc = gather_h(hs, gw, lane);   // self term, pre-scaled
    int e = beg;
    for (; e + 8 <= end; e += 8) {
        int s0 = g_csr[e],     s1 = g_csr[e + 1], s2 = g_csr[e + 2], s3 = g_csr[e + 3];
        int s4 = g_csr[e + 4], s5 = g_csr[e + 5], s6 = g_csr[e + 6], s7 = g_csr[e + 7];
        float4 v0 = gather_h(hs, s0, lane);
        float4 v1 = gather_h(hs, s1, lane);
        float4 v2 = gather_h(hs, s2, lane);
        float4 v3 = gather_h(hs, s3, lane);
        float4 v4 = gather_h(hs, s4, lane);
        float4 v5 = gather_h(hs, s5, lane);
        float4 v6 = gather_h(hs, s6, lane);
        float4 v7 = gather_h(hs, s7, lane);
        acc.x += (v0.x + v1.x) + (v2.x + v3.x) + (v4.x + v5.x) + (v6.x + v7.x);
        acc.y += (v0.y + v1.y) + (v2.y + v3.y) + (v4.y + v5.y) + (v6.y + v7.y);
        acc.z += (v0.z + v1.z) + (v2.z + v3.z) + (v4.z + v5.z) + (v6.z + v7.z);
        acc.w += (v0.w + v1.w) + (v2.w + v3.w) + (v4.w + v5.w) + (v6.w + v7.w);
    }
    for (; e < end; e++) {
        float4 v = gather_h(hs, g_csr[e], lane);
        acc.x += v.x; acc.y += v.y; acc.z += v.z; acc.w += v.w;
    }
    float dd = g_dis[gw];
    float4 b = *(const float4*)(bias + lane * 4);
    __half2 o0 = __float22half2_rn(make_float2(
        fmaxf(acc.x * dd + b.x, 0.f), fmaxf(acc.y * dd + b.y, 0.f)));
    __half2 o1 = __float22half2_rn(make_float2(
        fmaxf(acc.z * dd + b.z, 0.f), fmaxf(acc.w * dd + b.w, 0.f)));
    if (FUSE) {
        uint2 raw = *(const uint2*)(prev + (long)gw * 128 + lane * 4);
        o0 = __hadd2(o0, *(__half2*)&raw.x);
        o1 = __hadd2(o1, *(__half2*)&raw.y);
    }
    uint2 pack;
    pack.x = *(unsigned*)&o0;
    pack.y = *(unsigned*)&o1;
    *(uint2*)(xo + (long)gw * 128 + lane * 4) = pack;
}

// ---------------- launch ---------------------------------------------------
extern "C" void kernel_launch(void* const* d_in, const int* in_sizes, int n_in,
                              void* d_out, int out_size)
{
    const float* x  = (const float*)d_in[0];
    const void*  ei = d_in[1];
    const float* W1 = (const float*)d_in[2];
    const float* b1 = (const float*)d_in[3];
    const float* W2 = (const float*)d_in[4];
    const float* b2 = (const float*)d_in[5];
    const float* Wo = (const float*)d_in[6];
    const float* bo = (const float*)d_in[7];
    float* out = (float*)d_out;

    __half *hs, *x1, *xs;
    float* dis;
    cudaGetSymbolAddress((void**)&hs,  g_hs);
    cudaGetSymbolAddress((void**)&x1,  g_x1);
    cudaGetSymbolAddress((void**)&xs,  g_xs);
    cudaGetSymbolAddress((void**)&dis, g_dis);

    const int M = N_NODES;
    int gB  = (M + 127) / 128;
    int gE8 = (N_EDGES + 2047) / 2048;
    int gAg = (M * 32 + 255) / 256;

    k_init<<<1, 1024>>>(ei);
    k_hist<<<gE8, 256>>>(ei);
    k_scan1<<<SCAN_NB, SCAN_T>>>();
    k_scan3<<<SCAN_NB, SCAN_T>>>();
    k_fill<<<gE8, 256>>>(ei);

    gemm_h<float><<<gB, 256>>>(x, W1, hs, dis, M);
    aggregate_s<false><<<gAg, 256>>>(hs, b1, nullptr, x1);
    gemm_h<__half><<<gB, 256>>>(x1, W2, hs, dis, M);
    aggregate_s<true><<<gAg, 256>>>(hs, b2, x1, xs);    // xs = x1 + x2
    gemm_out_h<<<gB, 256>>>(xs, Wo, bo, out, M);
}

// round 17
// speedup vs baseline: 1.7306x; 1.0678x over previous
#include <cuda_runtime.h>
#include <cuda_fp16.h>
#include <mma.h>
#include <math.h>

using namespace nvcuda;

#define N_NODES 100000
#define N_PAD   100096
#define N_EDGES 1600000
#define CHN 128
#define OUTCH 64
#define SCAN_T 512
#define SCAN_NB ((N_NODES + SCAN_T - 1) / SCAN_T)   // 196

// ---------------- device scratch ------------------------------------------
__device__ int    g_cnt[N_NODES];        // statically 0; re-zeroed by k_scan3
__device__ int    g_row[N_NODES + 1];
__device__ int    g_cur[N_NODES];
__device__ float  g_dis[N_NODES];
__device__ int    g_csr[N_EDGES];
__device__ int    g_bsum[SCAN_NB];
__device__ __half g_hs[N_PAD * CHN];
__device__ __half g_x1[N_PAD * CHN];
__device__ __half g_xs[N_PAD * CHN];     // layer2 emits x1 + x2 (fused)

// ---------------- per-block dtype sniff ------------------------------------
// int64 edge ids < 2^31: every odd 32-bit word of the buffer is 0.
__device__ __forceinline__ int sniff_is64(const void* edges) {
    const int* p = (const int*)edges;
    int z = 0;
#pragma unroll
    for (int u = 0; u < 16; u++) z += (p[2 * u + 1] == 0);
    return z > 8;
}

// ---------------- hist ------------------------------------------------------
__global__ void k_hist(const void* __restrict__ edges) {
    int is64 = sniff_is64(edges);
    int base = (blockIdx.x * blockDim.x + threadIdx.x) * 8;
    if (base + 8 <= N_EDGES) {
        int d[8];
        if (is64) {
            const long long* p = (const long long*)edges + N_EDGES + base;
#pragma unroll
            for (int u = 0; u < 8; u++) d[u] = (int)p[u];
        } else {
            const int* p = (const int*)edges + N_EDGES + base;
#pragma unroll
            for (int u = 0; u < 8; u++) d[u] = p[u];
        }
#pragma unroll
        for (int u = 0; u < 8; u++) atomicAdd(&g_cnt[d[u]], 1);
    } else {
        for (int i = base; i < N_EDGES; i++) {
            int d;
            if (is64) d = (int)((const long long*)edges)[N_EDGES + i];
            else      d = ((const int*)edges)[N_EDGES + i];
            atomicAdd(&g_cnt[d], 1);
        }
    }
}

// ---------------- 2-kernel scan --------------------------------------------
__global__ void k_scan1() {
    __shared__ int s[SCAN_T];
    int i = blockIdx.x * SCAN_T + threadIdx.x;
    int v = (i < N_NODES) ? g_cnt[i] : 0;
    s[threadIdx.x] = v;
    __syncthreads();
    for (int off = SCAN_T / 2; off > 0; off >>= 1) {
        if (threadIdx.x < off) s[threadIdx.x] += s[threadIdx.x + off];
        __syncthreads();
    }
    if (threadIdx.x == 0) g_bsum[blockIdx.x] = s[0];
}

__global__ void k_scan3() {
    __shared__ int s[SCAN_T];
    __shared__ int bs[256];
    int t = threadIdx.x;
    if (t < 256) bs[t] = (t < SCAN_NB) ? g_bsum[t] : 0;
    __syncthreads();
    for (int off = 1; off < 256; off <<= 1) {
        int u = (t >= off && t < 256) ? bs[t - off] : 0;
        __syncthreads();
        if (t < 256) bs[t] += u;
        __syncthreads();
    }
    int boff = (blockIdx.x > 0) ? bs[blockIdx.x - 1] : 0;
    __syncthreads();

    int i = blockIdx.x * SCAN_T + t;
    int c = (i < N_NODES) ? g_cnt[i] : 0;
    s[t] = c;
    __syncthreads();
    for (int off = 1; off < SCAN_T; off <<= 1) {
        int u = (t >= off) ? s[t - off] : 0;
        __syncthreads();
        s[t] += u;
        __syncthreads();
    }
    if (i < N_NODES) {
        int excl = boff + s[t] - c;
        g_row[i] = excl;
        g_cur[i] = excl;
        g_dis[i] = rsqrtf((float)(c + 1));
        g_cnt[i] = 0;
        if (i == N_NODES - 1) g_row[N_NODES] = excl + c;
    }
}

// ---------------- fill body (device) ---------------------------------------
__device__ __forceinline__ void fill_body(const void* __restrict__ edges, int fb) {
    int is64 = sniff_is64(edges);
    int base = (fb * 256 + (int)threadIdx.x) * 8;
    if (base + 8 <= N_EDGES) {
        int sN[8], dN[8];
        if (is64) {
            const long long* ps = (const long long*)edges + base;
            const long long* pd = (const long long*)edges + N_EDGES + base;
#pragma unroll
            for (int u = 0; u < 8; u++) { sN[u] = (int)ps[u]; dN[u] = (int)pd[u]; }
        } else {
            const int* ps = (const int*)edges + base;
            const int* pd = (const int*)edges + N_EDGES + base;
#pragma unroll
            for (int u = 0; u < 8; u++) { sN[u] = ps[u]; dN[u] = pd[u]; }
        }
        int idx[8];
#pragma unroll
        for (int u = 0; u < 8; u++) idx[u] = atomicAdd(&g_cur[dN[u]], 1);
#pragma unroll
        for (int u = 0; u < 8; u++) g_csr[idx[u]] = sN[u];
    } else {
        for (int i = base; i < N_EDGES; i++) {
            int sN, dN;
            if (is64) {
                const long long* p = (const long long*)edges;
                sN = (int)p[i]; dN = (int)p[N_EDGES + i];
            } else {
                const int* p = (const int*)edges;
                sN = p[i]; dN = p[N_EDGES + i];
            }
            int idx = atomicAdd(&g_cur[dN], 1);
            g_csr[idx] = sN;
        }
    }
}

// ---------------- GEMM body (device): 128-row tile, K-chunk 64 -------------
struct GemmSmem {
    __half As[128][72];       // 18432 B
    __half Bs[64][136];       // 17408 B
};

template <typename AT>
__device__ __forceinline__ void gemm_body(
    GemmSmem& sm, const AT* __restrict__ A, const float* __restrict__ B,
    __half* __restrict__ out, const float* __restrict__ dis, int M, int bid)
{
    float (*stage)[16][20] = (float(*)[16][20])&sm.As[0][0];   // aliases

    int tid = threadIdx.x;
    int wid = tid >> 5;
    int lane = tid & 31;
    int wm = wid & 3;
    int wn = wid >> 2;
    int bm = bid * 128;

    wmma::fragment<wmma::accumulator, 16, 16, 16, float> acc[2][4];
#pragma unroll
    for (int i = 0; i < 2; i++)
#pragma unroll
        for (int j = 0; j < 4; j++) wmma::fill_fragment(acc[i][j], 0.f);

    for (int k0 = 0; k0 < 128; k0 += 64) {
#pragma unroll
        for (int h = 0; h < 8; h++) {
            int i4 = tid + h * 256;
            int r = i4 >> 4, c = (i4 & 15) * 4;
            __half2 p0, p1;
            if (bm + r < M) {
                if constexpr (sizeof(AT) == 4) {
                    float4 v = *(const float4*)((const float*)A + (long)(bm + r) * 128 + k0 + c);
                    p0 = __float22half2_rn(make_float2(v.x, v.y));
                    p1 = __float22half2_rn(make_float2(v.z, v.w));
                } else {
                    uint2 raw = *(const uint2*)((const __half*)A + (long)(bm + r) * 128 + k0 + c);
                    p0 = *(__half2*)&raw.x;
                    p1 = *(__half2*)&raw.y;
                }
            } else {
                p0 = __half2half2(__float2half(0.f));
                p1 = p0;
            }
            *(__half2*)&sm.As[r][c]     = p0;
            *(__half2*)&sm.As[r][c + 2] = p1;
        }
#pragma unroll
        for (int h = 0; h < 8; h++) {
            int i4 = tid + h * 256;
            int r = i4 >> 5, c = (i4 & 31) * 4;
            float4 v = *(const float4*)(B + (long)(k0 + r) * 128 + c);
            *(__half2*)&sm.Bs[r][c]     = __float22half2_rn(make_float2(v.x, v.y));
            *(__half2*)&sm.Bs[r][c + 2] = __float22half2_rn(make_float2(v.z, v.w));
        }
        __syncthreads();
#pragma unroll
        for (int kk = 0; kk < 4; kk++) {
            wmma::fragment<wmma::matrix_a, 16, 16, 16, __half, wmma::row_major> af[2];
            wmma::fragment<wmma::matrix_b, 16, 16, 16, __half, wmma::row_major> bf[4];
#pragma unroll
            for (int i = 0; i < 2; i++)
                wmma::load_matrix_sync(af[i], &sm.As[wm * 32 + i * 16][kk * 16], 72);
#pragma unroll
            for (int j = 0; j < 4; j++)
                wmma::load_matrix_sync(bf[j], &sm.Bs[kk * 16][wn * 64 + j * 16], 136);
#pragma unroll
            for (int i = 0; i < 2; i++)
#pragma unroll
                for (int j = 0; j < 4; j++)
                    wmma::mma_sync(acc[i][j], af[i], bf[j], acc[i][j]);
        }
        __syncthreads();
    }
#pragma unroll
    for (int i = 0; i < 2; i++)
#pragma unroll
        for (int j = 0; j < 4; j++) {
            wmma::store_matrix_sync(&stage[wid][0][0], acc[i][j], 20, wmma::mem_row_major);
            __syncwarp();
            int r = bm + wm * 32 + i * 16 + (lane >> 1);
            float dsc = (r < M) ? dis[r] : 0.f;
            const float* srow = &stage[wid][lane >> 1][(lane & 1) * 8];
            __half2 h0 = __float22half2_rn(make_float2(srow[0] * dsc, srow[1] * dsc));
            __half2 h1 = __float22half2_rn(make_float2(srow[2] * dsc, srow[3] * dsc));
            __half2 h2 = __float22half2_rn(make_float2(srow[4] * dsc, srow[5] * dsc));
            __half2 h3 = __float22half2_rn(make_float2(srow[6] * dsc, srow[7] * dsc));
            uint4 pack;
            pack.x = *(unsigned*)&h0;
            pack.y = *(unsigned*)&h1;
            pack.z = *(unsigned*)&h2;
            pack.w = *(unsigned*)&h3;
            *(uint4*)(out + (long)r * 128 + wn * 64 + j * 16 + (lane & 1) * 8) = pack;
            __syncwarp();
        }
}

// ---------------- fused: GEMM1 (blocks < gemmBlocks) ∥ fill (rest) --------
__global__ __launch_bounds__(256, 2) void k_gemm1_fill(
    const float* __restrict__ A, const float* __restrict__ B,
    __half* __restrict__ out, const float* __restrict__ dis, int M,
    const void* __restrict__ edges, int gemmBlocks)
{
    __shared__ GemmSmem sm;
    if ((int)blockIdx.x < gemmBlocks) {
        gemm_body<float>(sm, A, B, out, dis, M, blockIdx.x);
    } else {
        fill_body(edges, blockIdx.x - gemmBlocks);
    }
}

// ---------------- layer-2 GEMM (standalone) --------------------------------
__global__ __launch_bounds__(256, 2) void gemm2_h(
    const __half* __restrict__ A, const float* __restrict__ B,
    __half* __restrict__ out, const float* __restrict__ dis, int M)
{
    __shared__ GemmSmem sm;
    gemm_body<__half>(sm, A, B, out, dis, M, blockIdx.x);
}

// ---------------- fp16 output GEMM: xs[M,128] @ Wo[128,64] + bo -----------
__global__ __launch_bounds__(256, 2) void gemm_out_h(
    const __half* __restrict__ A, const float* __restrict__ B,
    const float* __restrict__ bias, float* __restrict__ out, int M)
{
    __shared__ __half As[128][72];
    __shared__ __half Bs[64][72];
    __shared__ float  Bt[16][72];
    int tid = threadIdx.x;
    int wid = tid >> 5;
    int bm = blockIdx.x * 128;

    for (int i = tid; i < 16 * 64; i += 256) Bt[i >> 6][i & 63] = bias[i & 63];
    __syncthreads();

    wmma::fragment<wmma::accumulator, 16, 16, 16, float> acc[4];
#pragma unroll
    for (int j = 0; j < 4; j++)
        wmma::load_matrix_sync(acc[j], &Bt[0][j * 16], 72, wmma::mem_row_major);

    for (int k0 = 0; k0 < 128; k0 += 64) {
#pragma unroll
        for (int h = 0; h < 8; h++) {
            int i4 = tid + h * 256;
            int r = i4 >> 4, c = (i4 & 15) * 4;
            __half2 p0, p1;
            if (bm + r < M) {
                uint2 raw = *(const uint2*)(A + (long)(bm + r) * 128 + k0 + c);
                p0 = *(__half2*)&raw.x;
                p1 = *(__half2*)&raw.y;
            } else {
                p0 = __half2half2(__float2half(0.f));
                p1 = p0;
            }
            *(__half2*)&As[r][c]     = p0;
            *(__half2*)&As[r][c + 2] = p1;
        }
#pragma unroll
        for (int h = 0; h < 4; h++) {
            int i4 = tid + h * 256;
            int r = i4 >> 4, c = (i4 & 15) * 4;
            float4 v = *(const float4*)(B + (long)(k0 + r) * 64 + c);
            *(__half2*)&Bs[r][c]     = __float22half2_rn(make_float2(v.x, v.y));
            *(__half2*)&Bs[r][c + 2] = __float22half2_rn(make_float2(v.z, v.w));
        }
        __syncthreads();
#pragma unroll
        for (int kk = 0; kk < 4; kk++) {
            wmma::fragment<wmma::matrix_a, 16, 16, 16, __half, wmma::row_major> af;
            wmma::fragment<wmma::matrix_b, 16, 16, 16, __half, wmma::row_major> bf[4];
            wmma::load_matrix_sync(af, &As[wid * 16][kk * 16], 72);
#pragma unroll
            for (int j = 0; j < 4; j++)
                wmma::load_matrix_sync(bf[j], &Bs[kk * 16][j * 16], 72);
#pragma unroll
            for (int j = 0; j < 4; j++)
                wmma::mma_sync(acc[j], af, bf[j], acc[j]);
        }
        __syncthreads();
    }
    int r = bm + wid * 16;
    if (r + 16 <= M) {
#pragma unroll
        for (int j = 0; j < 4; j++)
            wmma::store_matrix_sync(out + (long)r * 64 + j * 16,
                                    acc[j], 64, wmma::mem_row_major);
    }
}

// ---------------- aggregation: warp/node, 8-wide; optional +prev fusion ---
__device__ __forceinline__ float4 gather_h(const __half* hs, int s, int lane) {
    uint2 raw = *(const uint2*)(hs + (long)s * 128 + lane * 4);
    float2 a = __half22float2(*(__half2*)&raw.x);
    float2 b = __half22float2(*(__half2*)&raw.y);
    return make_float4(a.x, a.y, b.x, b.y);
}

template <bool FUSE>
__global__ __launch_bounds__(256) void aggregate_s(
    const __half* __restrict__ hs, const float* __restrict__ bias,
    const __half* __restrict__ prev, __half* __restrict__ xo)
{
    int gw = (blockIdx.x * blockDim.x + threadIdx.x) >> 5;
    int lane = threadIdx.x & 31;
    if (gw >= N_NODES) return;
    int beg = g_row[gw];
    int end = g_row[gw + 1];
    float4 acc = gather_h(hs, gw, lane);   // self term, pre-scaled
    int e = beg;
    for (; e + 8 <= end; e += 8) {
        int s0 = g_csr[e],     s1 = g_csr[e + 1], s2 = g_csr[e + 2], s3 = g_csr[e + 3];
        int s4 = g_csr[e + 4], s5 = g_csr[e + 5], s6 = g_csr[e + 6], s7 = g_csr[e + 7];
        float4 v0 = gather_h(hs, s0, lane);
        float4 v1 = gather_h(hs, s1, lane);
        float4 v2 = gather_h(hs, s2, lane);
        float4 v3 = gather_h(hs, s3, lane);
        float4 v4 = gather_h(hs, s4, lane);
        float4 v5 = gather_h(hs, s5, lane);
        float4 v6 = gather_h(hs, s6, lane);
        float4 v7 = gather_h(hs, s7, lane);
        acc.x += (v0.x + v1.x) + (v2.x + v3.x) + (v4.x + v5.x) + (v6.x + v7.x);
        acc.y += (v0.y + v1.y) + (v2.y + v3.y) + (v4.y + v5.y) + (v6.y + v7.y);
        acc.z += (v0.z + v1.z) + (v2.z + v3.z) + (v4.z + v5.z) + (v6.z + v7.z);
        acc.w += (v0.w + v1.w) + (v2.w + v3.w) + (v4.w + v5.w) + (v6.w + v7.w);
    }
    for (; e < end; e++) {
        float4 v = gather_h(hs, g_csr[e], lane);
        acc.x += v.x; acc.y += v.y; acc.z += v.z; acc.w += v.w;
    }
    float dd = g_dis[gw];
    float4 b = *(const float4*)(bias + lane * 4);
    __half2 o0 = __float22half2_rn(make_float2(
        fmaxf(acc.x * dd + b.x, 0.f), fmaxf(acc.y * dd + b.y, 0.f)));
    __half2 o1 = __float22half2_rn(make_float2(
        fmaxf(acc.z * dd + b.z, 0.f), fmaxf(acc.w * dd + b.w, 0.f)));
    if (FUSE) {
        uint2 raw = *(const uint2*)(prev + (long)gw * 128 + lane * 4);
        o0 = __hadd2(o0, *(__half2*)&raw.x);
        o1 = __hadd2(o1, *(__half2*)&raw.y);
    }
    uint2 pack;
    pack.x = *(unsigned*)&o0;
    pack.y = *(unsigned*)&o1;
    *(uint2*)(xo + (long)gw * 128 + lane * 4) = pack;
}

// ---------------- launch ---------------------------------------------------
extern "C" void kernel_launch(void* const* d_in, const int* in_sizes, int n_in,
                              void* d_out, int out_size)
{
    const float* x  = (const float*)d_in[0];
    const void*  ei = d_in[1];
    const float* W1 = (const float*)d_in[2];
    const float* b1 = (const float*)d_in[3];
    const float* W2 = (const float*)d_in[4];
    const float* b2 = (const float*)d_in[5];
    const float* Wo = (const float*)d_in[6];
    const float* bo = (const float*)d_in[7];
    float* out = (float*)d_out;

    __half *hs, *x1, *xs;
    float* dis;
    cudaGetSymbolAddress((void**)&hs,  g_hs);
    cudaGetSymbolAddress((void**)&x1,  g_x1);
    cudaGetSymbolAddress((void**)&xs,  g_xs);
    cudaGetSymbolAddress((void**)&dis, g_dis);

    const int M = N_NODES;
    int gB  = (M + 127) / 128;                 // 782
    int gE8 = (N_EDGES + 2047) / 2048;         // 782
    int gAg = (M * 32 + 255) / 256;

    k_hist<<<gE8, 256>>>(ei);
    k_scan1<<<SCAN_NB, SCAN_T>>>();
    k_scan3<<<SCAN_NB, SCAN_T>>>();
    k_gemm1_fill<<<gB + gE8, 256>>>(x, W1, hs, dis, M, ei, gB);   // GEMM1 ∥ fill
    aggregate_s<false><<<gAg, 256>>>(hs, b1, nullptr, x1);
    gemm2_h<<<gB, 256>>>(x1, W2, hs, dis, M);
    aggregate_s<true><<<gAg, 256>>>(hs, b2, x1, xs);              // xs = x1 + x2
    gemm_out_h<<<gB, 256>>>(xs, Wo, bo, out, M);
}